// round 13
// baseline (speedup 1.0000x reference)
#include <cuda_runtime.h>
#include <cstdint>

#define BB 8
#define LL 384
#define CC 512
#define NHH 8
#define DKK 64
#define NLL 4
#define RIN 53
#define RHH 32

__device__ float g_mask[BB * LL];
__device__ int   g_flag;
__device__ float g_h[(size_t)BB * LL * CC];
__device__ float g_q[(size_t)BB * NHH * LL * DKK];
__device__ float g_k[(size_t)BB * NHH * LL * DKK];
__device__ float g_v[(size_t)BB * NHH * LL * DKK];
__device__ float g_refw[(size_t)NLL * BB * NHH * LL * LL];
__device__ float g_sc[(size_t)BB * NHH * LL * LL];
__device__ float g_ao[(size_t)BB * LL * CC];
__device__ float g_t1[(size_t)BB * LL * CC];

// ---------- tf32 helpers ----------
__device__ __forceinline__ float to_tf32(float x) {
    uint32_t r; asm("cvt.rna.tf32.f32 %0, %1;" : "=r"(r) : "f"(x));
    return __uint_as_float(r);
}
__device__ __forceinline__ void split_tf32(float x, float& hi, float& lo) {
    hi = to_tf32(x); lo = to_tf32(x - hi);
}
__device__ __forceinline__ void mma_tf32(float* c, const uint32_t* a, uint32_t b0, uint32_t b1) {
    asm("mma.sync.aligned.m16n8k8.row.col.f32.tf32.tf32.f32 "
        "{%0,%1,%2,%3},{%4,%5,%6,%7},{%8,%9},{%0,%1,%2,%3};"
        : "+f"(c[0]), "+f"(c[1]), "+f"(c[2]), "+f"(c[3])
        : "r"(a[0]), "r"(a[1]), "r"(a[2]), "r"(a[3]), "r"(b0), "r"(b1));
}

#define W2OFF(r) ((r) * 8 + ((r) & ~1) * 2)

// ---------- mask detection ----------
__global__ void k_detect(const unsigned char* __restrict__ p) {
    __shared__ int sHi, sF3;
    if (threadIdx.x == 0) { sHi = 0; sF3 = 0; }
    __syncthreads();
    int hi = 0, f3 = 0;
    for (int i = threadIdx.x; i < BB * LL; i += blockDim.x) {
        unsigned char v = p[i];
        if (v) {
            if ((i & 3) == 3 && v == 0x3F) f3 = 1;
            else if ((i & 3) != 0) hi = 1;
        }
    }
    if (hi) sHi = 1;
    if (f3) sF3 = 1;
    __syncthreads();
    if (threadIdx.x == 0) g_flag = sF3 ? 2 : (sHi ? 1 : 0);
}

__global__ void k_mask(const unsigned char* __restrict__ p) {
    int i = blockIdx.x * 256 + threadIdx.x;
    if (i >= BB * LL) return;
    int flag = g_flag;
    float m;
    if (flag == 2)      m = (((const float*)p)[i] != 0.0f) ? 1.0f : 0.0f;
    else if (flag == 1) m = (p[i] != 0) ? 1.0f : 0.0f;
    else                m = (p[4 * i] != 0) ? 1.0f : 0.0f;
    g_mask[i] = m;
}

__global__ void k_hinit(const float* __restrict__ x) {
    size_t idx = (size_t)blockIdx.x * 256 + threadIdx.x;
    g_h[idx] = x[idx] * g_mask[idx >> 9];
}

// ============ k_ref: stage A in 1xTF32 (softmax-protected), float2 W1 frags ============
#define RF_W1F  0                          // [7 ks][16 ntg][32 lane][2] = 7168
#define RF_W2P  (RF_W1F + 7*16*32*2)
#define RF_B2   (RF_W2P + 1536)
#define RF_MASK (RF_B2 + 32)
#define RF_RC   (RF_MASK + 384)
#define REF_SMEM_FLOATS (RF_RC + 56*72)

__global__ void __launch_bounds__(256, 2)
k_ref(const float* __restrict__ refCov, const float* __restrict__ Wr1,
      const float* __restrict__ br1, const float* __restrict__ Wr2,
      const float* __restrict__ br2) {
    extern __shared__ float sm[];
    float*  sW1f = sm + RF_W1F;
    float*  sW2p = sm + RF_W2P;
    float*  sB2  = sm + RF_B2;
    float*  sMask = sm + RF_MASK;
    float*  sRC  = sm + RF_RC;

    int t = threadIdx.x, lane = t & 31, wid = t >> 5;
    int g = lane >> 2, tg = lane & 3;
    int wm4 = wid & 3;
    int wn2 = wid >> 2;
    int bx = blockIdx.x;
    int b = bx / LL, i = bx % LL;

    // fragment-major W1 (tf32 hi only, packed float2 per lane)
    for (int idx = t; idx < 7 * 16 * 32; idx += 256) {
        int ks = idx / 512, rem = idx & 511;
        int ntg = rem >> 5, ln = rem & 31;
        int lg = ln >> 2, ltg = ln & 3;
        int col = ntg * 8 + lg;
        int l = col >> 5, m = col & 31;
        int ka = ks * 8 + ltg, kb = ka + 4;
        float xa = (ka < RIN) ? Wr1[(size_t)(l * RIN + ka) * RHH + m] : 0.0f;
        float xb = (kb < RIN) ? Wr1[(size_t)(l * RIN + kb) * RHH + m] : 0.0f;
        float2 fr; fr.x = to_tf32(xa); fr.y = to_tf32(xb);
        *(float2*)&sW1f[(size_t)idx * 2] = fr;
    }
    for (int idx = t; idx < 128 * 8; idx += 256)
        sW2p[W2OFF(idx >> 3) + (idx & 7)] = Wr2[idx];
    if (t < 32) sB2[t] = br2[t];
    for (int idx = t; idx < LL; idx += 256) sMask[idx] = g_mask[b * LL + idx];
    for (int idx = t; idx < 3 * 72; idx += 256)
        sRC[53 * 72 + idx] = 0.0f;

    float b1r[8][2];
#pragma unroll
    for (int nt = 0; nt < 8; nt++)
#pragma unroll
        for (int u = 0; u < 2; u++) {
            int col = wn2 * 64 + nt * 8 + 2 * tg + u;
            b1r[nt][u] = br1[(col >> 5) * RHH + (col & 31)];
        }
    __syncthreads();

    const float* rcbase = refCov + (size_t)(b * LL + i) * LL * RIN;
    int mb = wm4 * 16;

    for (int j0 = 0; j0 < LL; j0 += 64) {
        for (int idx = t; idx < 64 * RIN; idx += 256) {
            int jl = idx / RIN, k = idx % RIN;
            sRC[k * 72 + jl] = rcbase[(size_t)(j0 + jl) * RIN + k];
        }
        __syncthreads();

        float acc[8][4];
#pragma unroll
        for (int nt = 0; nt < 8; nt++)
#pragma unroll
            for (int q = 0; q < 4; q++) acc[nt][q] = 0.0f;

#pragma unroll
        for (int ks = 0; ks < 7; ks++) {
            int kk = ks * 8;
            uint32_t ah[4];
            ah[0] = __float_as_uint(to_tf32(sRC[(kk + tg) * 72 + mb + g]));
            ah[1] = __float_as_uint(to_tf32(sRC[(kk + tg) * 72 + mb + g + 8]));
            ah[2] = __float_as_uint(to_tf32(sRC[(kk + tg + 4) * 72 + mb + g]));
            ah[3] = __float_as_uint(to_tf32(sRC[(kk + tg + 4) * 72 + mb + g + 8]));
            const float2* wf = (const float2*)&sW1f[(size_t)(((ks * 16) + wn2 * 8) * 32 + lane) * 2];
#pragma unroll
            for (int nt = 0; nt < 8; nt++) {
                float2 bf = wf[nt * 32];
                mma_tf32(acc[nt], ah, __float_as_uint(bf.x), __float_as_uint(bf.y));
            }
        }

#pragma unroll
        for (int lg = 0; lg < 2; lg++) {
            int l = wn2 * 2 + lg;
            float p[2][8];
#pragma unroll
            for (int rh = 0; rh < 2; rh++)
#pragma unroll
                for (int h = 0; h < 8; h++) p[rh][h] = 0.0f;
#pragma unroll
            for (int nt4 = 0; nt4 < 4; nt4++) {
                int nt = lg * 4 + nt4;
#pragma unroll
                for (int u = 0; u < 2; u++) {
                    float hv0 = fmaxf(acc[nt][u]     + b1r[nt][u], 0.0f);
                    float hv1 = fmaxf(acc[nt][2 + u] + b1r[nt][u], 0.0f);
                    int m = nt4 * 8 + 2 * tg + u;
                    const float* w2p = &sW2p[W2OFF(l * 32 + m)];
                    float4 wa = *(const float4*)w2p;
                    float4 wb = *(const float4*)(w2p + 4);
                    p[0][0] += hv0 * wa.x; p[0][1] += hv0 * wa.y;
                    p[0][2] += hv0 * wa.z; p[0][3] += hv0 * wa.w;
                    p[0][4] += hv0 * wb.x; p[0][5] += hv0 * wb.y;
                    p[0][6] += hv0 * wb.z; p[0][7] += hv0 * wb.w;
                    p[1][0] += hv1 * wa.x; p[1][1] += hv1 * wa.y;
                    p[1][2] += hv1 * wa.z; p[1][3] += hv1 * wa.w;
                    p[1][4] += hv1 * wb.x; p[1][5] += hv1 * wb.y;
                    p[1][6] += hv1 * wb.z; p[1][7] += hv1 * wb.w;
                }
            }
#pragma unroll
            for (int msk = 1; msk <= 2; msk <<= 1)
#pragma unroll
                for (int rh = 0; rh < 2; rh++)
#pragma unroll
                    for (int h = 0; h < 8; h++)
                        p[rh][h] += __shfl_xor_sync(0xffffffffu, p[rh][h], msk);

#pragma unroll
            for (int rh = 0; rh < 2; rh++) {
                int j = j0 + mb + g + rh * 8;
                float mv = sMask[j];
#pragma unroll
                for (int hh = 0; hh < 2; hh++) {
                    int h = 2 * tg + hh;
                    float val = (mv != 0.0f) ? (p[rh][h] + sB2[l * 8 + h]) : -1e30f;
                    g_refw[((size_t)(l * 64 + b * 8 + h) * LL + i) * LL + j] = val;
                }
            }
        }
        __syncthreads();
    }
}

// ======== k_mm v4 (R10): 128x64 CTA tile, warp 32x32, raw smem + inline split ========
template <int MODE>
__global__ void __launch_bounds__(256) k_mm(
        const float* __restrict__ W0, const float* __restrict__ W1,
        const float* __restrict__ W2, const float* __restrict__ b0,
        const float* __restrict__ b1, const float* __restrict__ b2) {
    __shared__ float As[128 * 20], Bs[16 * 72];
    int sel = (MODE == 1) ? (blockIdx.y >> 3) : 0;
    const float* A    = (MODE == 0) ? g_ao : g_h;
    const float* W    = (sel == 0) ? W0 : (sel == 1) ? W1 : W2;
    const float* bias = (sel == 0) ? b0 : (sel == 1) ? b1 : b2;
    int m0 = blockIdx.x * 128;
    int n0 = ((MODE == 1) ? (blockIdx.y & 7) : blockIdx.y) * 64;
    int t = threadIdx.x, lane = t & 31, wid = t >> 5;
    int g = lane >> 2, tg = lane & 3;
    int wm = wid & 3, wn = wid >> 2;
    int ar = t >> 1, ac8 = (t & 1) * 8;
    int wr = t >> 4, wc = t & 15;

    float acc[2][4][4] = {};

    for (int k0 = 0; k0 < CC; k0 += 16) {
        *(float4*)&As[ar * 20 + ac8] =
            *(const float4*)&A[(size_t)(m0 + ar) * CC + k0 + ac8];
        *(float4*)&As[ar * 20 + ac8 + 4] =
            *(const float4*)&A[(size_t)(m0 + ar) * CC + k0 + ac8 + 4];
        *(float4*)&Bs[wr * 72 + wc * 4] =
            *(const float4*)&W[(size_t)(k0 + wr) * CC + n0 + wc * 4];
        __syncthreads();

#pragma unroll
        for (int kk = 0; kk < 16; kk += 8) {
            uint32_t ah[2][4], al[2][4];
#pragma unroll
            for (int mt = 0; mt < 2; mt++) {
                int mb = wm * 32 + mt * 16;
                float xv[4];
                xv[0] = As[(mb + g) * 20 + kk + tg];
                xv[1] = As[(mb + g + 8) * 20 + kk + tg];
                xv[2] = As[(mb + g) * 20 + kk + tg + 4];
                xv[3] = As[(mb + g + 8) * 20 + kk + tg + 4];
#pragma unroll
                for (int q = 0; q < 4; q++) {
                    float hv, lv; split_tf32(xv[q], hv, lv);
                    ah[mt][q] = __float_as_uint(hv);
                    al[mt][q] = __float_as_uint(lv);
                }
            }
#pragma unroll
            for (int nt = 0; nt < 4; nt++) {
                int nb = wn * 32 + nt * 8;
                float x0 = Bs[(kk + tg) * 72 + nb + g];
                float x1 = Bs[(kk + tg + 4) * 72 + nb + g];
                float h0, l0, h1, l1;
                split_tf32(x0, h0, l0); split_tf32(x1, h1, l1);
                uint32_t bh0 = __float_as_uint(h0), bh1 = __float_as_uint(h1);
                uint32_t bl0 = __float_as_uint(l0), bl1 = __float_as_uint(l1);
#pragma unroll
                for (int mt = 0; mt < 2; mt++) {
                    mma_tf32(acc[mt][nt], ah[mt], bh0, bh1);
                    mma_tf32(acc[mt][nt], al[mt], bh0, bh1);
                    mma_tf32(acc[mt][nt], ah[mt], bl0, bl1);
                }
            }
        }
        __syncthreads();
    }

#pragma unroll
    for (int mt = 0; mt < 2; mt++) {
#pragma unroll
        for (int nt = 0; nt < 4; nt++) {
#pragma unroll
            for (int rh = 0; rh < 2; rh++) {
                int m = m0 + wm * 32 + mt * 16 + g + rh * 8;
                int n = n0 + wn * 32 + nt * 8 + 2 * tg;
                float v0 = acc[mt][nt][rh * 2]     + bias[n];
                float v1 = acc[mt][nt][rh * 2 + 1] + bias[n + 1];
                if (MODE == 0) {
                    *(float2*)&g_t1[(size_t)m * CC + n] = make_float2(v0, v1);
                } else {
                    int bi = m / LL, ii = m % LL, nh = n >> 6, d = n & 63;
                    float* OUT = (sel == 0) ? g_q : (sel == 1) ? g_k : g_v;
                    *(float2*)&OUT[((size_t)(bi * NHH + nh) * LL + ii) * DKK + d] =
                        make_float2(v0, v1);
                }
            }
        }
    }
}

// ---------- scores: 64x64 tile, raw smem + inline split ----------
__global__ void __launch_bounds__(256) k_scores_mma() {
    __shared__ float As[64 * 20], Bs[64 * 20];
    int z = blockIdx.z, b = z >> 3;
    int i0 = blockIdx.x * 64, j0 = blockIdx.y * 64;
    const float* Q = g_q + (size_t)z * LL * DKK;
    const float* K = g_k + (size_t)z * LL * DKK;
    int t = threadIdx.x, lane = t & 31, wid = t >> 5;
    int g = lane >> 2, tg = lane & 3;
    int wm = wid & 1, wn = wid >> 1;
    int ar = t >> 2, ac = t & 3;
    float acc[2][2][4] = {};

    for (int k0 = 0; k0 < DKK; k0 += 16) {
        *(float4*)&As[ar * 20 + ac * 4] =
            *(const float4*)&Q[(size_t)(i0 + ar) * DKK + k0 + ac * 4];
        *(float4*)&Bs[ar * 20 + ac * 4] =
            *(const float4*)&K[(size_t)(j0 + ar) * DKK + k0 + ac * 4];
        __syncthreads();

#pragma unroll
        for (int kk = 0; kk < 16; kk += 8) {
            uint32_t ah[2][4], al[2][4];
#pragma unroll
            for (int mt = 0; mt < 2; mt++) {
                int mb = wm * 32 + mt * 16;
                float xv[4];
                xv[0] = As[(mb + g) * 20 + kk + tg];
                xv[1] = As[(mb + g + 8) * 20 + kk + tg];
                xv[2] = As[(mb + g) * 20 + kk + tg + 4];
                xv[3] = As[(mb + g + 8) * 20 + kk + tg + 4];
#pragma unroll
                for (int q = 0; q < 4; q++) {
                    float hv, lv; split_tf32(xv[q], hv, lv);
                    ah[mt][q] = __float_as_uint(hv);
                    al[mt][q] = __float_as_uint(lv);
                }
            }
#pragma unroll
            for (int nt = 0; nt < 2; nt++) {
                int nb = wn * 16 + nt * 8;
                float x0 = Bs[(nb + g) * 20 + kk + tg];
                float x1 = Bs[(nb + g) * 20 + kk + tg + 4];
                float h0, l0, h1, l1;
                split_tf32(x0, h0, l0); split_tf32(x1, h1, l1);
                uint32_t bh0 = __float_as_uint(h0), bh1 = __float_as_uint(h1);
                uint32_t bl0 = __float_as_uint(l0), bl1 = __float_as_uint(l1);
#pragma unroll
                for (int mt = 0; mt < 2; mt++) {
                    mma_tf32(acc[mt][nt], ah[mt], bh0, bh1);
                    mma_tf32(acc[mt][nt], al[mt], bh0, bh1);
                    mma_tf32(acc[mt][nt], ah[mt], bl0, bl1);
                }
            }
        }
        __syncthreads();
    }

    float* out = g_sc + (size_t)z * LL * LL;
#pragma unroll
    for (int mt = 0; mt < 2; mt++) {
#pragma unroll
        for (int rh = 0; rh < 2; rh++) {
            int i = i0 + wm * 32 + mt * 16 + g + rh * 8;
            float mi = g_mask[b * LL + i];
#pragma unroll
            for (int nt = 0; nt < 2; nt++) {
                int j = j0 + wn * 16 + nt * 8 + 2 * tg;
                float mj0 = g_mask[b * LL + j];
                float mj1 = g_mask[b * LL + j + 1];
                float v0 = (mi != 0.0f && mj0 != 0.0f) ? acc[mt][nt][rh * 2] * 0.125f : -1e30f;
                float v1 = (mi != 0.0f && mj1 != 0.0f) ? acc[mt][nt][rh * 2 + 1] * 0.125f : -1e30f;
                *(float2*)&out[(size_t)i * LL + j] = make_float2(v0, v1);
            }
        }
    }
}

// ---------- dual softmax + combine ----------
__global__ void k_softcomb(int l) {
    int gw = blockIdx.x * 4 + (threadIdx.x >> 5);
    int lane = threadIdx.x & 31;
    int row_i = gw % LL;
    int z = gw / LL;
    int b = z >> 3;
    float* sc = g_sc + (size_t)z * LL * LL + (size_t)row_i * LL;
    if (g_mask[b * LL + row_i] == 0.0f) {
        for (int j = lane; j < LL; j += 32) sc[j] = 0.0f;
        return;
    }
    const float* rw = g_refw + (((size_t)l * BB * NHH + z) * LL + row_i) * LL;
    float vals[12], rv[12];
    float mx = -3.4e38f, rmx = -3.4e38f;
#pragma unroll
    for (int r = 0; r < 12; r++) {
        vals[r] = sc[lane + r * 32]; mx = fmaxf(mx, vals[r]);
        rv[r] = rw[lane + r * 32];   rmx = fmaxf(rmx, rv[r]);
    }
#pragma unroll
    for (int o = 16; o > 0; o >>= 1) {
        mx  = fmaxf(mx,  __shfl_xor_sync(0xffffffffu, mx, o));
        rmx = fmaxf(rmx, __shfl_xor_sync(0xffffffffu, rmx, o));
    }
    float s = 0.0f, rs = 0.0f;
#pragma unroll
    for (int r = 0; r < 12; r++) {
        vals[r] = __expf(vals[r] - mx); s += vals[r];
        rv[r]   = __expf(rv[r] - rmx);  rs += rv[r];
    }
#pragma unroll
    for (int o = 16; o > 0; o >>= 1) {
        s  += __shfl_xor_sync(0xffffffffu, s, o);
        rs += __shfl_xor_sync(0xffffffffu, rs, o);
    }
    float inv = 0.5f / s, rinv = 0.5f / rs;
#pragma unroll
    for (int r = 0; r < 12; r++)
        sc[lane + r * 32] = vals[r] * inv + rv[r] * rinv;
}

// ---------- av: 64x64 tile, K=384, raw smem + inline split ----------
__global__ void __launch_bounds__(256) k_av_mma() {
    __shared__ float As[64 * 20], Bs[16 * 72];
    int z = blockIdx.y, b = z >> 3, nh = z & 7;
    const float* Am = g_sc + (size_t)z * LL * LL;
    const float* V  = g_v + (size_t)z * LL * DKK;
    int m0 = blockIdx.x * 64;
    int t = threadIdx.x, lane = t & 31, wid = t >> 5;
    int g = lane >> 2, tg = lane & 3;
    int wm = wid & 1, wn = wid >> 1;
    int ar = t >> 2, ac = t & 3;
    int wr = t >> 4, wc = t & 15;
    float acc[2][2][4] = {};

    for (int k0 = 0; k0 < LL; k0 += 16) {
        *(float4*)&As[ar * 20 + ac * 4] =
            *(const float4*)&Am[(size_t)(m0 + ar) * LL + k0 + ac * 4];
        *(float4*)&Bs[wr * 72 + wc * 4] =
            *(const float4*)&V[(size_t)(k0 + wr) * DKK + wc * 4];
        __syncthreads();

#pragma unroll
        for (int kk = 0; kk < 16; kk += 8) {
            uint32_t ah[2][4], al[2][4];
#pragma unroll
            for (int mt = 0; mt < 2; mt++) {
                int mb = wm * 32 + mt * 16;
                float xv[4];
                xv[0] = As[(mb + g) * 20 + kk + tg];
                xv[1] = As[(mb + g + 8) * 20 + kk + tg];
                xv[2] = As[(mb + g) * 20 + kk + tg + 4];
                xv[3] = As[(mb + g + 8) * 20 + kk + tg + 4];
#pragma unroll
                for (int q = 0; q < 4; q++) {
                    float hv, lv; split_tf32(xv[q], hv, lv);
                    ah[mt][q] = __float_as_uint(hv);
                    al[mt][q] = __float_as_uint(lv);
                }
            }
#pragma unroll
            for (int nt = 0; nt < 2; nt++) {
                int nb = wn * 16 + nt * 8;
                float x0 = Bs[(kk + tg) * 72 + nb + g];
                float x1 = Bs[(kk + tg + 4) * 72 + nb + g];
                float h0, l0, h1, l1;
                split_tf32(x0, h0, l0); split_tf32(x1, h1, l1);
                uint32_t bh0 = __float_as_uint(h0), bh1 = __float_as_uint(h1);
                uint32_t bl0 = __float_as_uint(l0), bl1 = __float_as_uint(l1);
#pragma unroll
                for (int mt = 0; mt < 2; mt++) {
                    mma_tf32(acc[mt][nt], ah[mt], bh0, bh1);
                    mma_tf32(acc[mt][nt], al[mt], bh0, bh1);
                    mma_tf32(acc[mt][nt], ah[mt], bl0, bl1);
                }
            }
        }
        __syncthreads();
    }

#pragma unroll
    for (int mt = 0; mt < 2; mt++) {
#pragma unroll
        for (int nt = 0; nt < 2; nt++) {
#pragma unroll
            for (int rh = 0; rh < 2; rh++) {
                int i = m0 + wm * 32 + mt * 16 + g + rh * 8;
                int d = wn * 16 + nt * 8 + 2 * tg;
                *(float2*)&g_ao[((size_t)(b * LL + i)) * CC + nh * DKK + d] =
                    make_float2(acc[mt][nt][rh * 2], acc[mt][nt][rh * 2 + 1]);
            }
        }
    }
}

// ---------- residual + layernorm ----------
template <int FINAL>
__global__ void k_ln(const float* __restrict__ gam, const float* __restrict__ bet) {
    __shared__ float red[8];
    int r = blockIdx.x, t = threadIdx.x;
    const float* a = g_h + (size_t)r * CC;
    const float* bb = g_t1 + (size_t)r * CC;
    float v[4];
    float s = 0.0f;
#pragma unroll
    for (int q = 0; q < 4; q++) {
        int cidx = t + q * 128;
        float x = FINAL ? a[cidx] : (a[cidx] + bb[cidx]);
        v[q] = x;
        s += x;
    }
#pragma unroll
    for (int o = 16; o > 0; o >>= 1) s += __shfl_xor_sync(0xffffffffu, s, o);
    if ((t & 31) == 0) red[t >> 5] = s;
    __syncthreads();
    float mu = (red[0] + red[1] + red[2] + red[3]) * (1.0f / 512.0f);
    float vs = 0.0f;
#pragma unroll
    for (int q = 0; q < 4; q++) { float d = v[q] - mu; vs += d * d; }
#pragma unroll
    for (int o = 16; o > 0; o >>= 1) vs += __shfl_xor_sync(0xffffffffu, vs, o);
    if ((t & 31) == 0) red[4 + (t >> 5)] = vs;
    __syncthreads();
    float var = (red[4] + red[5] + red[6] + red[7]) * (1.0f / 512.0f);
    float rsr = rsqrtf(var + 1e-5f);
    float* out = FINAL ? (g_t1 + (size_t)r * CC) : (g_h + (size_t)r * CC);
#pragma unroll
    for (int q = 0; q < 4; q++) {
        int cidx = t + q * 128;
        out[cidx] = (v[q] - mu) * rsr * gam[cidx] + bet[cidx];
    }
}

// ---------- final masked sum ----------
__global__ void k_finred(float* __restrict__ out) {
    int b = blockIdx.x;
    int cidx = blockIdx.y * 128 + threadIdx.x;
    float s = 0.0f;
#pragma unroll 4
    for (int i = 0; i < LL; i++)
        s += g_mask[b * LL + i] * g_t1[((size_t)(b * LL + i)) * CC + cidx];
    out[b * CC + cidx] = s;
}

// ---------- host launch ----------
extern "C" void kernel_launch(void* const* d_in, const int* in_sizes, int n_in,
                              void* d_out, int out_size) {
    const float* x            = (const float*)d_in[0];
    const unsigned char* mraw = (const unsigned char*)d_in[1];
    const float* refCov       = (const float*)d_in[2];
    const float* Wq  = (const float*)d_in[3];
    const float* bq  = (const float*)d_in[4];
    const float* Wk  = (const float*)d_in[5];
    const float* bk  = (const float*)d_in[6];
    const float* Wv  = (const float*)d_in[7];
    const float* bv  = (const float*)d_in[8];
    const float* Wo  = (const float*)d_in[9];
    const float* bo  = (const float*)d_in[10];
    const float* Wr1 = (const float*)d_in[11];
    const float* br1 = (const float*)d_in[12];
    const float* Wr2 = (const float*)d_in[13];
    const float* br2 = (const float*)d_in[14];
    const float* ln_g = (const float*)d_in[15];
    const float* ln_b = (const float*)d_in[16];
    const float* fn_g = (const float*)d_in[17];
    const float* fn_b = (const float*)d_in[18];
    (void)in_sizes; (void)n_in; (void)out_size;

    cudaFuncSetAttribute(k_ref, cudaFuncAttributeMaxDynamicSharedMemorySize,
                         REF_SMEM_FLOATS * (int)sizeof(float));

    k_detect<<<1, 256>>>(mraw);
    k_mask<<<(BB * LL + 255) / 256, 256>>>(mraw);
    k_hinit<<<(BB * LL * CC) / 256, 256>>>(x);
    k_ref<<<BB * LL, 256, REF_SMEM_FLOATS * sizeof(float)>>>(refCov, Wr1, br1, Wr2, br2);

    for (int l = 0; l < NLL; l++) {
        const float* wq = Wq + (size_t)l * CC * CC;
        const float* wk = Wk + (size_t)l * CC * CC;
        const float* wv = Wv + (size_t)l * CC * CC;
        const float* wo = Wo + (size_t)l * CC * CC;
        k_mm<1><<<dim3(24, 24), 256>>>(wq, wk, wv, bq + l * CC, bk + l * CC, bv + l * CC);
        k_scores_mma<<<dim3(6, 6, BB * NHH), 256>>>();
        k_softcomb<<<(BB * NHH * LL) / 4, 128>>>(l);
        k_av_mma<<<dim3(6, BB * NHH), 256>>>();
        k_mm<0><<<dim3(24, 8), 256>>>(wo, bo + l * CC, nullptr, bo + l * CC, nullptr, nullptr);
        k_ln<0><<<BB * LL, 128>>>(ln_g + l * CC, ln_b + l * CC);
    }
    k_ln<1><<<BB * LL, 128>>>(fn_g, fn_b);
    k_finred<<<dim3(BB, CC / 128), 128>>>((float*)d_out);
}

// round 14
// speedup vs baseline: 1.4252x; 1.4252x over previous
#include <cuda_runtime.h>
#include <cstdint>

#define BB 8
#define LL 384
#define CC 512
#define NHH 8
#define DKK 64
#define NLL 4
#define RIN 53
#define RHH 32

__device__ float g_mask[BB * LL];
__device__ int   g_flag;
__device__ float g_h[(size_t)BB * LL * CC];
__device__ float g_q[(size_t)BB * NHH * LL * DKK];
__device__ float g_k[(size_t)BB * NHH * LL * DKK];
__device__ float g_v[(size_t)BB * NHH * LL * DKK];
__device__ float g_refw[(size_t)NLL * BB * NHH * LL * LL];
__device__ float g_sc[(size_t)BB * NHH * LL * LL];
__device__ float g_ao[(size_t)BB * LL * CC];
__device__ float g_t1[(size_t)BB * LL * CC];

// ---------- tf32 helpers ----------
__device__ __forceinline__ float to_tf32(float x) {
    uint32_t r; asm("cvt.rna.tf32.f32 %0, %1;" : "=r"(r) : "f"(x));
    return __uint_as_float(r);
}
__device__ __forceinline__ void split_tf32(float x, float& hi, float& lo) {
    hi = to_tf32(x); lo = to_tf32(x - hi);
}
__device__ __forceinline__ void mma_tf32(float* c, const uint32_t* a, uint32_t b0, uint32_t b1) {
    asm("mma.sync.aligned.m16n8k8.row.col.f32.tf32.tf32.f32 "
        "{%0,%1,%2,%3},{%4,%5,%6,%7},{%8,%9},{%0,%1,%2,%3};"
        : "+f"(c[0]), "+f"(c[1]), "+f"(c[2]), "+f"(c[3])
        : "r"(a[0]), "r"(a[1]), "r"(a[2]), "r"(a[3]), "r"(b0), "r"(b1));
}

#define W2OFF(r) ((r) * 8 + ((r) & ~1) * 2)

// ---------- mask detection ----------
__global__ void k_detect(const unsigned char* __restrict__ p) {
    __shared__ int sHi, sF3;
    if (threadIdx.x == 0) { sHi = 0; sF3 = 0; }
    __syncthreads();
    int hi = 0, f3 = 0;
    for (int i = threadIdx.x; i < BB * LL; i += blockDim.x) {
        unsigned char v = p[i];
        if (v) {
            if ((i & 3) == 3 && v == 0x3F) f3 = 1;
            else if ((i & 3) != 0) hi = 1;
        }
    }
    if (hi) sHi = 1;
    if (f3) sF3 = 1;
    __syncthreads();
    if (threadIdx.x == 0) g_flag = sF3 ? 2 : (sHi ? 1 : 0);
}

__global__ void k_mask(const unsigned char* __restrict__ p) {
    int i = blockIdx.x * 256 + threadIdx.x;
    if (i >= BB * LL) return;
    int flag = g_flag;
    float m;
    if (flag == 2)      m = (((const float*)p)[i] != 0.0f) ? 1.0f : 0.0f;
    else if (flag == 1) m = (p[i] != 0) ? 1.0f : 0.0f;
    else                m = (p[4 * i] != 0) ? 1.0f : 0.0f;
    g_mask[i] = m;
}

__global__ void k_hinit(const float* __restrict__ x) {
    size_t idx = (size_t)blockIdx.x * 256 + threadIdx.x;
    g_h[idx] = x[idx] * g_mask[idx >> 9];
}

// ============ k_ref: pair-MLP via mma; frag-major 3xTF32 W1, raw RC + inline split ============
#define RF_W1F  0
#define RF_W2P  (RF_W1F + 7*16*32*4)
#define RF_B2   (RF_W2P + 1536)
#define RF_MASK (RF_B2 + 32)
#define RF_RC   (RF_MASK + 384)
#define REF_SMEM_FLOATS (RF_RC + 56*72)

__global__ void __launch_bounds__(256, 2)
k_ref(const float* __restrict__ refCov, const float* __restrict__ Wr1,
      const float* __restrict__ br1, const float* __restrict__ Wr2,
      const float* __restrict__ br2) {
    extern __shared__ float sm[];
    float*  sW1f = sm + RF_W1F;
    float*  sW2p = sm + RF_W2P;
    float*  sB2  = sm + RF_B2;
    float*  sMask = sm + RF_MASK;
    float*  sRC  = sm + RF_RC;

    int t = threadIdx.x, lane = t & 31, wid = t >> 5;
    int g = lane >> 2, tg = lane & 3;
    int wm4 = wid & 3;
    int wn2 = wid >> 2;
    int bx = blockIdx.x;
    int b = bx / LL, i = bx % LL;

    for (int idx = t; idx < 7 * 16 * 32; idx += 256) {
        int ks = idx / 512, rem = idx & 511;
        int ntg = rem >> 5, ln = rem & 31;
        int lg = ln >> 2, ltg = ln & 3;
        int col = ntg * 8 + lg;
        int l = col >> 5, m = col & 31;
        int ka = ks * 8 + ltg, kb = ka + 4;
        float xa = (ka < RIN) ? Wr1[(size_t)(l * RIN + ka) * RHH + m] : 0.0f;
        float xb = (kb < RIN) ? Wr1[(size_t)(l * RIN + kb) * RHH + m] : 0.0f;
        float ha, la, hb, lb;
        split_tf32(xa, ha, la); split_tf32(xb, hb, lb);
        float4 fr; fr.x = ha; fr.y = hb; fr.z = la; fr.w = lb;
        *(float4*)&sW1f[(size_t)idx * 4] = fr;
    }
    for (int idx = t; idx < 128 * 8; idx += 256)
        sW2p[W2OFF(idx >> 3) + (idx & 7)] = Wr2[idx];
    if (t < 32) sB2[t] = br2[t];
    for (int idx = t; idx < LL; idx += 256) sMask[idx] = g_mask[b * LL + idx];
    for (int idx = t; idx < 3 * 72; idx += 256)
        sRC[53 * 72 + idx] = 0.0f;

    float b1r[8][2];
#pragma unroll
    for (int nt = 0; nt < 8; nt++)
#pragma unroll
        for (int u = 0; u < 2; u++) {
            int col = wn2 * 64 + nt * 8 + 2 * tg + u;
            b1r[nt][u] = br1[(col >> 5) * RHH + (col & 31)];
        }
    __syncthreads();

    const float* rcbase = refCov + (size_t)(b * LL + i) * LL * RIN;
    int mb = wm4 * 16;

    for (int j0 = 0; j0 < LL; j0 += 64) {
        for (int idx = t; idx < 64 * RIN; idx += 256) {
            int jl = idx / RIN, k = idx % RIN;
            sRC[k * 72 + jl] = rcbase[(size_t)(j0 + jl) * RIN + k];
        }
        __syncthreads();

        float acc[8][4];
#pragma unroll
        for (int nt = 0; nt < 8; nt++)
#pragma unroll
            for (int q = 0; q < 4; q++) acc[nt][q] = 0.0f;

#pragma unroll
        for (int ks = 0; ks < 7; ks++) {
            int kk = ks * 8;
            float xv[4];
            xv[0] = sRC[(kk + tg) * 72 + mb + g];
            xv[1] = sRC[(kk + tg) * 72 + mb + g + 8];
            xv[2] = sRC[(kk + tg + 4) * 72 + mb + g];
            xv[3] = sRC[(kk + tg + 4) * 72 + mb + g + 8];
            uint32_t ah[4], al[4];
#pragma unroll
            for (int q = 0; q < 4; q++) {
                float hv, lv; split_tf32(xv[q], hv, lv);
                ah[q] = __float_as_uint(hv);
                al[q] = __float_as_uint(lv);
            }
            const float4* wf = (const float4*)&sW1f[(size_t)(((ks * 16) + wn2 * 8) * 32 + lane) * 4];
#pragma unroll
            for (int nt = 0; nt < 8; nt++) {
                float4 bf = wf[nt * 32];
                uint32_t bh0 = __float_as_uint(bf.x), bh1 = __float_as_uint(bf.y);
                uint32_t bl0 = __float_as_uint(bf.z), bl1 = __float_as_uint(bf.w);
                mma_tf32(acc[nt], ah, bh0, bh1);
                mma_tf32(acc[nt], al, bh0, bh1);
                mma_tf32(acc[nt], ah, bl0, bl1);
            }
        }

#pragma unroll
        for (int lg = 0; lg < 2; lg++) {
            int l = wn2 * 2 + lg;
            float p[2][8];
#pragma unroll
            for (int rh = 0; rh < 2; rh++)
#pragma unroll
                for (int h = 0; h < 8; h++) p[rh][h] = 0.0f;
#pragma unroll
            for (int nt4 = 0; nt4 < 4; nt4++) {
                int nt = lg * 4 + nt4;
#pragma unroll
                for (int u = 0; u < 2; u++) {
                    float hv0 = fmaxf(acc[nt][u]     + b1r[nt][u], 0.0f);
                    float hv1 = fmaxf(acc[nt][2 + u] + b1r[nt][u], 0.0f);
                    int m = nt4 * 8 + 2 * tg + u;
                    const float* w2p = &sW2p[W2OFF(l * 32 + m)];
                    float4 wa = *(const float4*)w2p;
                    float4 wb = *(const float4*)(w2p + 4);
                    p[0][0] += hv0 * wa.x; p[0][1] += hv0 * wa.y;
                    p[0][2] += hv0 * wa.z; p[0][3] += hv0 * wa.w;
                    p[0][4] += hv0 * wb.x; p[0][5] += hv0 * wb.y;
                    p[0][6] += hv0 * wb.z; p[0][7] += hv0 * wb.w;
                    p[1][0] += hv1 * wa.x; p[1][1] += hv1 * wa.y;
                    p[1][2] += hv1 * wa.z; p[1][3] += hv1 * wa.w;
                    p[1][4] += hv1 * wb.x; p[1][5] += hv1 * wb.y;
                    p[1][6] += hv1 * wb.z; p[1][7] += hv1 * wb.w;
                }
            }
#pragma unroll
            for (int msk = 1; msk <= 2; msk <<= 1)
#pragma unroll
                for (int rh = 0; rh < 2; rh++)
#pragma unroll
                    for (int h = 0; h < 8; h++)
                        p[rh][h] += __shfl_xor_sync(0xffffffffu, p[rh][h], msk);

#pragma unroll
            for (int rh = 0; rh < 2; rh++) {
                int j = j0 + mb + g + rh * 8;
                float mv = sMask[j];
#pragma unroll
                for (int hh = 0; hh < 2; hh++) {
                    int h = 2 * tg + hh;
                    float val = (mv != 0.0f) ? (p[rh][h] + sB2[l * 8 + h]) : -1e30f;
                    g_refw[((size_t)(l * 64 + b * 8 + h) * LL + i) * LL + j] = val;
                }
            }
        }
        __syncthreads();
    }
}

// ======== k_mm: 128x64 CTA tile, warp 32x32, raw smem + inline split ========
template <int MODE>
__global__ void __launch_bounds__(256) k_mm(
        const float* __restrict__ W0, const float* __restrict__ W1,
        const float* __restrict__ W2, const float* __restrict__ b0,
        const float* __restrict__ b1, const float* __restrict__ b2) {
    __shared__ float As[128 * 20], Bs[16 * 72];
    int sel = (MODE == 1) ? (blockIdx.y >> 3) : 0;
    const float* A    = (MODE == 0) ? g_ao : g_h;
    const float* W    = (sel == 0) ? W0 : (sel == 1) ? W1 : W2;
    const float* bias = (sel == 0) ? b0 : (sel == 1) ? b1 : b2;
    int m0 = blockIdx.x * 128;
    int n0 = ((MODE == 1) ? (blockIdx.y & 7) : blockIdx.y) * 64;
    int t = threadIdx.x, lane = t & 31, wid = t >> 5;
    int g = lane >> 2, tg = lane & 3;
    int wm = wid & 3, wn = wid >> 2;
    int ar = t >> 1, ac8 = (t & 1) * 8;
    int wr = t >> 4, wc = t & 15;

    float acc[2][4][4] = {};

    for (int k0 = 0; k0 < CC; k0 += 16) {
        *(float4*)&As[ar * 20 + ac8] =
            *(const float4*)&A[(size_t)(m0 + ar) * CC + k0 + ac8];
        *(float4*)&As[ar * 20 + ac8 + 4] =
            *(const float4*)&A[(size_t)(m0 + ar) * CC + k0 + ac8 + 4];
        *(float4*)&Bs[wr * 72 + wc * 4] =
            *(const float4*)&W[(size_t)(k0 + wr) * CC + n0 + wc * 4];
        __syncthreads();

#pragma unroll
        for (int kk = 0; kk < 16; kk += 8) {
            uint32_t ah[2][4], al[2][4];
#pragma unroll
            for (int mt = 0; mt < 2; mt++) {
                int mb = wm * 32 + mt * 16;
                float xv[4];
                xv[0] = As[(mb + g) * 20 + kk + tg];
                xv[1] = As[(mb + g + 8) * 20 + kk + tg];
                xv[2] = As[(mb + g) * 20 + kk + tg + 4];
                xv[3] = As[(mb + g + 8) * 20 + kk + tg + 4];
#pragma unroll
                for (int q = 0; q < 4; q++) {
                    float hv, lv; split_tf32(xv[q], hv, lv);
                    ah[mt][q] = __float_as_uint(hv);
                    al[mt][q] = __float_as_uint(lv);
                }
            }
#pragma unroll
            for (int nt = 0; nt < 4; nt++) {
                int nb = wn * 32 + nt * 8;
                float x0 = Bs[(kk + tg) * 72 + nb + g];
                float x1 = Bs[(kk + tg + 4) * 72 + nb + g];
                float h0, l0, h1, l1;
                split_tf32(x0, h0, l0); split_tf32(x1, h1, l1);
                uint32_t bh0 = __float_as_uint(h0), bh1 = __float_as_uint(h1);
                uint32_t bl0 = __float_as_uint(l0), bl1 = __float_as_uint(l1);
#pragma unroll
                for (int mt = 0; mt < 2; mt++) {
                    mma_tf32(acc[mt][nt], ah[mt], bh0, bh1);
                    mma_tf32(acc[mt][nt], al[mt], bh0, bh1);
                    mma_tf32(acc[mt][nt], ah[mt], bl0, bl1);
                }
            }
        }
        __syncthreads();
    }

#pragma unroll
    for (int mt = 0; mt < 2; mt++) {
#pragma unroll
        for (int nt = 0; nt < 4; nt++) {
#pragma unroll
            for (int rh = 0; rh < 2; rh++) {
                int m = m0 + wm * 32 + mt * 16 + g + rh * 8;
                int n = n0 + wn * 32 + nt * 8 + 2 * tg;
                float v0 = acc[mt][nt][rh * 2]     + bias[n];
                float v1 = acc[mt][nt][rh * 2 + 1] + bias[n + 1];
                if (MODE == 0) {
                    *(float2*)&g_t1[(size_t)m * CC + n] = make_float2(v0, v1);
                } else {
                    int bi = m / LL, ii = m % LL, nh = n >> 6, d = n & 63;
                    float* OUT = (sel == 0) ? g_q : (sel == 1) ? g_k : g_v;
                    *(float2*)&OUT[((size_t)(bi * NHH + nh) * LL + ii) * DKK + d] =
                        make_float2(v0, v1);
                }
            }
        }
    }
}

// ---------- scores: 64x64 tile, raw smem + inline split ----------
__global__ void __launch_bounds__(256) k_scores_mma() {
    __shared__ float As[64 * 20], Bs[64 * 20];
    int z = blockIdx.z, b = z >> 3;
    int i0 = blockIdx.x * 64, j0 = blockIdx.y * 64;
    const float* Q = g_q + (size_t)z * LL * DKK;
    const float* K = g_k + (size_t)z * LL * DKK;
    int t = threadIdx.x, lane = t & 31, wid = t >> 5;
    int g = lane >> 2, tg = lane & 3;
    int wm = wid & 1, wn = wid >> 1;
    int ar = t >> 2, ac = t & 3;
    float acc[2][2][4] = {};

    for (int k0 = 0; k0 < DKK; k0 += 16) {
        *(float4*)&As[ar * 20 + ac * 4] =
            *(const float4*)&Q[(size_t)(i0 + ar) * DKK + k0 + ac * 4];
        *(float4*)&Bs[ar * 20 + ac * 4] =
            *(const float4*)&K[(size_t)(j0 + ar) * DKK + k0 + ac * 4];
        __syncthreads();

#pragma unroll
        for (int kk = 0; kk < 16; kk += 8) {
            uint32_t ah[2][4], al[2][4];
#pragma unroll
            for (int mt = 0; mt < 2; mt++) {
                int mb = wm * 32 + mt * 16;
                float xv[4];
                xv[0] = As[(mb + g) * 20 + kk + tg];
                xv[1] = As[(mb + g + 8) * 20 + kk + tg];
                xv[2] = As[(mb + g) * 20 + kk + tg + 4];
                xv[3] = As[(mb + g + 8) * 20 + kk + tg + 4];
#pragma unroll
                for (int q = 0; q < 4; q++) {
                    float hv, lv; split_tf32(xv[q], hv, lv);
                    ah[mt][q] = __float_as_uint(hv);
                    al[mt][q] = __float_as_uint(lv);
                }
            }
#pragma unroll
            for (int nt = 0; nt < 2; nt++) {
                int nb = wn * 16 + nt * 8;
                float x0 = Bs[(nb + g) * 20 + kk + tg];
                float x1 = Bs[(nb + g) * 20 + kk + tg + 4];
                float h0, l0, h1, l1;
                split_tf32(x0, h0, l0); split_tf32(x1, h1, l1);
                uint32_t bh0 = __float_as_uint(h0), bh1 = __float_as_uint(h1);
                uint32_t bl0 = __float_as_uint(l0), bl1 = __float_as_uint(l1);
#pragma unroll
                for (int mt = 0; mt < 2; mt++) {
                    mma_tf32(acc[mt][nt], ah[mt], bh0, bh1);
                    mma_tf32(acc[mt][nt], al[mt], bh0, bh1);
                    mma_tf32(acc[mt][nt], ah[mt], bl0, bl1);
                }
            }
        }
        __syncthreads();
    }

    float* out = g_sc + (size_t)z * LL * LL;
#pragma unroll
    for (int mt = 0; mt < 2; mt++) {
#pragma unroll
        for (int rh = 0; rh < 2; rh++) {
            int i = i0 + wm * 32 + mt * 16 + g + rh * 8;
            float mi = g_mask[b * LL + i];
#pragma unroll
            for (int nt = 0; nt < 2; nt++) {
                int j = j0 + wn * 16 + nt * 8 + 2 * tg;
                float mj0 = g_mask[b * LL + j];
                float mj1 = g_mask[b * LL + j + 1];
                float v0 = (mi != 0.0f && mj0 != 0.0f) ? acc[mt][nt][rh * 2] * 0.125f : -1e30f;
                float v1 = (mi != 0.0f && mj1 != 0.0f) ? acc[mt][nt][rh * 2 + 1] * 0.125f : -1e30f;
                *(float2*)&out[(size_t)i * LL + j] = make_float2(v0, v1);
            }
        }
    }
}

// ---------- dual softmax + combine ----------
__global__ void k_softcomb(int l) {
    int gw = blockIdx.x * 4 + (threadIdx.x >> 5);
    int lane = threadIdx.x & 31;
    int row_i = gw % LL;
    int z = gw / LL;
    int b = z >> 3;
    float* sc = g_sc + (size_t)z * LL * LL + (size_t)row_i * LL;
    if (g_mask[b * LL + row_i] == 0.0f) {
        for (int j = lane; j < LL; j += 32) sc[j] = 0.0f;
        return;
    }
    const float* rw = g_refw + (((size_t)l * BB * NHH + z) * LL + row_i) * LL;
    float vals[12], rv[12];
    float mx = -3.4e38f, rmx = -3.4e38f;
#pragma unroll
    for (int r = 0; r < 12; r++) {
        vals[r] = sc[lane + r * 32]; mx = fmaxf(mx, vals[r]);
        rv[r] = rw[lane + r * 32];   rmx = fmaxf(rmx, rv[r]);
    }
#pragma unroll
    for (int o = 16; o > 0; o >>= 1) {
        mx  = fmaxf(mx,  __shfl_xor_sync(0xffffffffu, mx, o));
        rmx = fmaxf(rmx, __shfl_xor_sync(0xffffffffu, rmx, o));
    }
    float s = 0.0f, rs = 0.0f;
#pragma unroll
    for (int r = 0; r < 12; r++) {
        vals[r] = __expf(vals[r] - mx); s += vals[r];
        rv[r]   = __expf(rv[r] - rmx);  rs += rv[r];
    }
#pragma unroll
    for (int o = 16; o > 0; o >>= 1) {
        s  += __shfl_xor_sync(0xffffffffu, s, o);
        rs += __shfl_xor_sync(0xffffffffu, rs, o);
    }
    float inv = 0.5f / s, rinv = 0.5f / rs;
#pragma unroll
    for (int r = 0; r < 12; r++)
        sc[lane + r * 32] = vals[r] * inv + rv[r] * rinv;
}

// ---------- av: 64x64 tile, K=384, raw smem + inline split ----------
__global__ void __launch_bounds__(256) k_av_mma() {
    __shared__ float As[64 * 20], Bs[16 * 72];
    int z = blockIdx.y, b = z >> 3, nh = z & 7;
    const float* Am = g_sc + (size_t)z * LL * LL;
    const float* V  = g_v + (size_t)z * LL * DKK;
    int m0 = blockIdx.x * 64;
    int t = threadIdx.x, lane = t & 31, wid = t >> 5;
    int g = lane >> 2, tg = lane & 3;
    int wm = wid & 1, wn = wid >> 1;
    int ar = t >> 2, ac = t & 3;
    int wr = t >> 4, wc = t & 15;
    float acc[2][2][4] = {};

    for (int k0 = 0; k0 < LL; k0 += 16) {
        *(float4*)&As[ar * 20 + ac * 4] =
            *(const float4*)&Am[(size_t)(m0 + ar) * LL + k0 + ac * 4];
        *(float4*)&Bs[wr * 72 + wc * 4] =
            *(const float4*)&V[(size_t)(k0 + wr) * DKK + wc * 4];
        __syncthreads();

#pragma unroll
        for (int kk = 0; kk < 16; kk += 8) {
            uint32_t ah[2][4], al[2][4];
#pragma unroll
            for (int mt = 0; mt < 2; mt++) {
                int mb = wm * 32 + mt * 16;
                float xv[4];
                xv[0] = As[(mb + g) * 20 + kk + tg];
                xv[1] = As[(mb + g + 8) * 20 + kk + tg];
                xv[2] = As[(mb + g) * 20 + kk + tg + 4];
                xv[3] = As[(mb + g + 8) * 20 + kk + tg + 4];
#pragma unroll
                for (int q = 0; q < 4; q++) {
                    float hv, lv; split_tf32(xv[q], hv, lv);
                    ah[mt][q] = __float_as_uint(hv);
                    al[mt][q] = __float_as_uint(lv);
                }
            }
#pragma unroll
            for (int nt = 0; nt < 2; nt++) {
                int nb = wn * 16 + nt * 8;
                float x0 = Bs[(kk + tg) * 72 + nb + g];
                float x1 = Bs[(kk + tg + 4) * 72 + nb + g];
                float h0, l0, h1, l1;
                split_tf32(x0, h0, l0); split_tf32(x1, h1, l1);
                uint32_t bh0 = __float_as_uint(h0), bh1 = __float_as_uint(h1);
                uint32_t bl0 = __float_as_uint(l0), bl1 = __float_as_uint(l1);
#pragma unroll
                for (int mt = 0; mt < 2; mt++) {
                    mma_tf32(acc[mt][nt], ah[mt], bh0, bh1);
                    mma_tf32(acc[mt][nt], al[mt], bh0, bh1);
                    mma_tf32(acc[mt][nt], ah[mt], bl0, bl1);
                }
            }
        }
        __syncthreads();
    }

#pragma unroll
    for (int mt = 0; mt < 2; mt++) {
#pragma unroll
        for (int nt = 0; nt < 2; nt++) {
#pragma unroll
            for (int rh = 0; rh < 2; rh++) {
                int i = m0 + wm * 32 + mt * 16 + g + rh * 8;
                int d = wn * 16 + nt * 8 + 2 * tg;
                *(float2*)&g_ao[((size_t)(b * LL + i)) * CC + nh * DKK + d] =
                    make_float2(acc[mt][nt][rh * 2], acc[mt][nt][rh * 2 + 1]);
            }
        }
    }
}

// ---------- residual + layernorm ----------
template <int FINAL>
__global__ void k_ln(const float* __restrict__ gam, const float* __restrict__ bet) {
    __shared__ float red[8];
    int r = blockIdx.x, t = threadIdx.x;
    const float* a = g_h + (size_t)r * CC;
    const float* bb = g_t1 + (size_t)r * CC;
    float v[4];
    float s = 0.0f;
#pragma unroll
    for (int q = 0; q < 4; q++) {
        int cidx = t + q * 128;
        float x = FINAL ? a[cidx] : (a[cidx] + bb[cidx]);
        v[q] = x;
        s += x;
    }
#pragma unroll
    for (int o = 16; o > 0; o >>= 1) s += __shfl_xor_sync(0xffffffffu, s, o);
    if ((t & 31) == 0) red[t >> 5] = s;
    __syncthreads();
    float mu = (red[0] + red[1] + red[2] + red[3]) * (1.0f / 512.0f);
    float vs = 0.0f;
#pragma unroll
    for (int q = 0; q < 4; q++) { float d = v[q] - mu; vs += d * d; }
#pragma unroll
    for (int o = 16; o > 0; o >>= 1) vs += __shfl_xor_sync(0xffffffffu, vs, o);
    if ((t & 31) == 0) red[4 + (t >> 5)] = vs;
    __syncthreads();
    float var = (red[4] + red[5] + red[6] + red[7]) * (1.0f / 512.0f);
    float rsr = rsqrtf(var + 1e-5f);
    float* out = FINAL ? (g_t1 + (size_t)r * CC) : (g_h + (size_t)r * CC);
#pragma unroll
    for (int q = 0; q < 4; q++) {
        int cidx = t + q * 128;
        out[cidx] = (v[q] - mu) * rsr * gam[cidx] + bet[cidx];
    }
}

// ---------- final masked sum ----------
__global__ void k_finred(float* __restrict__ out) {
    int b = blockIdx.x;
    int cidx = blockIdx.y * 128 + threadIdx.x;
    float s = 0.0f;
#pragma unroll 4
    for (int i = 0; i < LL; i++)
        s += g_mask[b * LL + i] * g_t1[((size_t)(b * LL + i)) * CC + cidx];
    out[b * CC + cidx] = s;
}

// ---------- host launch ----------
extern "C" void kernel_launch(void* const* d_in, const int* in_sizes, int n_in,
                              void* d_out, int out_size) {
    const float* x            = (const float*)d_in[0];
    const unsigned char* mraw = (const unsigned char*)d_in[1];
    const float* refCov       = (const float*)d_in[2];
    const float* Wq  = (const float*)d_in[3];
    const float* bq  = (const float*)d_in[4];
    const float* Wk  = (const float*)d_in[5];
    const float* bk  = (const float*)d_in[6];
    const float* Wv  = (const float*)d_in[7];
    const float* bv  = (const float*)d_in[8];
    const float* Wo  = (const float*)d_in[9];
    const float* bo  = (const float*)d_in[10];
    const float* Wr1 = (const float*)d_in[11];
    const float* br1 = (const float*)d_in[12];
    const float* Wr2 = (const float*)d_in[13];
    const float* br2 = (const float*)d_in[14];
    const float* ln_g = (const float*)d_in[15];
    const float* ln_b = (const float*)d_in[16];
    const float* fn_g = (const float*)d_in[17];
    const float* fn_b = (const float*)d_in[18];
    (void)in_sizes; (void)n_in; (void)out_size;

    cudaFuncSetAttribute(k_ref, cudaFuncAttributeMaxDynamicSharedMemorySize,
                         REF_SMEM_FLOATS * (int)sizeof(float));

    k_detect<<<1, 256>>>(mraw);
    k_mask<<<(BB * LL + 255) / 256, 256>>>(mraw);
    k_hinit<<<(BB * LL * CC) / 256, 256>>>(x);
    k_ref<<<BB * LL, 256, REF_SMEM_FLOATS * sizeof(float)>>>(refCov, Wr1, br1, Wr2, br2);

    for (int l = 0; l < NLL; l++) {
        const float* wq = Wq + (size_t)l * CC * CC;
        const float* wk = Wk + (size_t)l * CC * CC;
        const float* wv = Wv + (size_t)l * CC * CC;
        const float* wo = Wo + (size_t)l * CC * CC;
        k_mm<1><<<dim3(24, 24), 256>>>(wq, wk, wv, bq + l * CC, bk + l * CC, bv + l * CC);
        k_scores_mma<<<dim3(6, 6, BB * NHH), 256>>>();
        k_softcomb<<<(BB * NHH * LL) / 4, 128>>>(l);
        k_av_mma<<<dim3(6, BB * NHH), 256>>>();
        k_mm<0><<<dim3(24, 8), 256>>>(wo, bo + l * CC, nullptr, bo + l * CC, nullptr, nullptr);
        k_ln<0><<<BB * LL, 128>>>(ln_g + l * CC, ln_b + l * CC);
    }
    k_ln<1><<<BB * LL, 128>>>(fn_g, fn_b);
    k_finred<<<dim3(BB, CC / 128), 128>>>((float*)d_out);
}

// round 15
// speedup vs baseline: 1.4589x; 1.0236x over previous
#include <cuda_runtime.h>
#include <cstdint>

#define BB 8
#define LL 384
#define CC 512
#define NHH 8
#define DKK 64
#define NLL 4
#define RIN 53
#define RHH 32

__device__ float g_mask[BB * LL];
__device__ int   g_flag;
__device__ float g_h[(size_t)BB * LL * CC];
__device__ float g_q[(size_t)BB * NHH * LL * DKK];
__device__ float g_k[(size_t)BB * NHH * LL * DKK];
__device__ float g_v[(size_t)BB * NHH * LL * DKK];
__device__ float g_refw[(size_t)NLL * BB * NHH * LL * LL];
__device__ float g_sc[(size_t)BB * NHH * LL * LL];
__device__ float g_ao[(size_t)BB * LL * CC];
__device__ float g_t1[(size_t)BB * LL * CC];

// ---------- tf32 helpers ----------
__device__ __forceinline__ float to_tf32(float x) {
    uint32_t r; asm("cvt.rna.tf32.f32 %0, %1;" : "=r"(r) : "f"(x));
    return __uint_as_float(r);
}
__device__ __forceinline__ void split_tf32(float x, float& hi, float& lo) {
    hi = to_tf32(x); lo = to_tf32(x - hi);
}
__device__ __forceinline__ void mma_tf32(float* c, const uint32_t* a, uint32_t b0, uint32_t b1) {
    asm("mma.sync.aligned.m16n8k8.row.col.f32.tf32.tf32.f32 "
        "{%0,%1,%2,%3},{%4,%5,%6,%7},{%8,%9},{%0,%1,%2,%3};"
        : "+f"(c[0]), "+f"(c[1]), "+f"(c[2]), "+f"(c[3])
        : "r"(a[0]), "r"(a[1]), "r"(a[2]), "r"(a[3]), "r"(b0), "r"(b1));
}

// ---------- packed f32x2 helpers (sm_103a FFMA2) ----------
__device__ __forceinline__ unsigned long long pack2(float x, float y) {
    unsigned long long r;
    asm("mov.b64 %0, {%1, %2};" : "=l"(r) : "f"(x), "f"(y));
    return r;
}
__device__ __forceinline__ void unpack2(unsigned long long v, float& x, float& y) {
    asm("mov.b64 {%0, %1}, %2;" : "=f"(x), "=f"(y) : "l"(v));
}
__device__ __forceinline__ void fma2(unsigned long long& c, unsigned long long a, unsigned long long b) {
    asm("fma.rn.f32x2 %0, %1, %2, %0;" : "+l"(c) : "l"(a), "l"(b));
}
__device__ __forceinline__ unsigned long long add2(unsigned long long a, unsigned long long b) {
    unsigned long long r;
    asm("add.rn.f32x2 %0, %1, %2;" : "=l"(r) : "l"(a), "l"(b));
    return r;
}

#define W2OFF(r) ((r) * 8 + ((r) & ~1) * 2)

// ---------- mask detection ----------
__global__ void k_detect(const unsigned char* __restrict__ p) {
    __shared__ int sHi, sF3;
    if (threadIdx.x == 0) { sHi = 0; sF3 = 0; }
    __syncthreads();
    int hi = 0, f3 = 0;
    for (int i = threadIdx.x; i < BB * LL; i += blockDim.x) {
        unsigned char v = p[i];
        if (v) {
            if ((i & 3) == 3 && v == 0x3F) f3 = 1;
            else if ((i & 3) != 0) hi = 1;
        }
    }
    if (hi) sHi = 1;
    if (f3) sF3 = 1;
    __syncthreads();
    if (threadIdx.x == 0) g_flag = sF3 ? 2 : (sHi ? 1 : 0);
}

__global__ void k_mask(const unsigned char* __restrict__ p) {
    int i = blockIdx.x * 256 + threadIdx.x;
    if (i >= BB * LL) return;
    int flag = g_flag;
    float m;
    if (flag == 2)      m = (((const float*)p)[i] != 0.0f) ? 1.0f : 0.0f;
    else if (flag == 1) m = (p[i] != 0) ? 1.0f : 0.0f;
    else                m = (p[4 * i] != 0) ? 1.0f : 0.0f;
    g_mask[i] = m;
}

__global__ void k_hinit(const float* __restrict__ x) {
    size_t idx = (size_t)blockIdx.x * 256 + threadIdx.x;
    g_h[idx] = x[idx] * g_mask[idx >> 9];
}

// ============ k_ref: pair-MLP via mma; stage B packed FFMA2 ============
#define RF_W1F  0
#define RF_W2P  (RF_W1F + 7*16*32*4)
#define RF_B2   (RF_W2P + 1536)
#define RF_MASK (RF_B2 + 32)
#define RF_RC   (RF_MASK + 384)
#define REF_SMEM_FLOATS (RF_RC + 56*72)

__global__ void __launch_bounds__(256, 2)
k_ref(const float* __restrict__ refCov, const float* __restrict__ Wr1,
      const float* __restrict__ br1, const float* __restrict__ Wr2,
      const float* __restrict__ br2) {
    extern __shared__ float sm[];
    float*  sW1f = sm + RF_W1F;
    float*  sW2p = sm + RF_W2P;
    float*  sB2  = sm + RF_B2;
    float*  sMask = sm + RF_MASK;
    float*  sRC  = sm + RF_RC;

    int t = threadIdx.x, lane = t & 31, wid = t >> 5;
    int g = lane >> 2, tg = lane & 3;
    int wm4 = wid & 3;
    int wn2 = wid >> 2;
    int bx = blockIdx.x;
    int b = bx / LL, i = bx % LL;

    for (int idx = t; idx < 7 * 16 * 32; idx += 256) {
        int ks = idx / 512, rem = idx & 511;
        int ntg = rem >> 5, ln = rem & 31;
        int lg = ln >> 2, ltg = ln & 3;
        int col = ntg * 8 + lg;
        int l = col >> 5, m = col & 31;
        int ka = ks * 8 + ltg, kb = ka + 4;
        float xa = (ka < RIN) ? Wr1[(size_t)(l * RIN + ka) * RHH + m] : 0.0f;
        float xb = (kb < RIN) ? Wr1[(size_t)(l * RIN + kb) * RHH + m] : 0.0f;
        float ha, la, hb, lb;
        split_tf32(xa, ha, la); split_tf32(xb, hb, lb);
        float4 fr; fr.x = ha; fr.y = hb; fr.z = la; fr.w = lb;
        *(float4*)&sW1f[(size_t)idx * 4] = fr;
    }
    for (int idx = t; idx < 128 * 8; idx += 256)
        sW2p[W2OFF(idx >> 3) + (idx & 7)] = Wr2[idx];
    if (t < 32) sB2[t] = br2[t];
    for (int idx = t; idx < LL; idx += 256) sMask[idx] = g_mask[b * LL + idx];
    for (int idx = t; idx < 3 * 72; idx += 256)
        sRC[53 * 72 + idx] = 0.0f;

    float b1r[8][2];
#pragma unroll
    for (int nt = 0; nt < 8; nt++)
#pragma unroll
        for (int u = 0; u < 2; u++) {
            int col = wn2 * 64 + nt * 8 + 2 * tg + u;
            b1r[nt][u] = br1[(col >> 5) * RHH + (col & 31)];
        }
    __syncthreads();

    const float* rcbase = refCov + (size_t)(b * LL + i) * LL * RIN;
    int mb = wm4 * 16;

    for (int j0 = 0; j0 < LL; j0 += 64) {
        for (int idx = t; idx < 64 * RIN; idx += 256) {
            int jl = idx / RIN, k = idx % RIN;
            sRC[k * 72 + jl] = rcbase[(size_t)(j0 + jl) * RIN + k];
        }
        __syncthreads();

        float acc[8][4];
#pragma unroll
        for (int nt = 0; nt < 8; nt++)
#pragma unroll
            for (int q = 0; q < 4; q++) acc[nt][q] = 0.0f;

#pragma unroll
        for (int ks = 0; ks < 7; ks++) {
            int kk = ks * 8;
            float xv[4];
            xv[0] = sRC[(kk + tg) * 72 + mb + g];
            xv[1] = sRC[(kk + tg) * 72 + mb + g + 8];
            xv[2] = sRC[(kk + tg + 4) * 72 + mb + g];
            xv[3] = sRC[(kk + tg + 4) * 72 + mb + g + 8];
            uint32_t ah[4], al[4];
#pragma unroll
            for (int q = 0; q < 4; q++) {
                float hv, lv; split_tf32(xv[q], hv, lv);
                ah[q] = __float_as_uint(hv);
                al[q] = __float_as_uint(lv);
            }
            const float4* wf = (const float4*)&sW1f[(size_t)(((ks * 16) + wn2 * 8) * 32 + lane) * 4];
#pragma unroll
            for (int nt = 0; nt < 8; nt++) {
                float4 bf = wf[nt * 32];
                uint32_t bh0 = __float_as_uint(bf.x), bh1 = __float_as_uint(bf.y);
                uint32_t bl0 = __float_as_uint(bf.z), bl1 = __float_as_uint(bf.w);
                mma_tf32(acc[nt], ah, bh0, bh1);
                mma_tf32(acc[nt], al, bh0, bh1);
                mma_tf32(acc[nt], ah, bl0, bl1);
            }
        }

        // stage B: packed f32x2 — pp[rh][j] = (p[rh][2j], p[rh][2j+1])
#pragma unroll
        for (int lg = 0; lg < 2; lg++) {
            int l = wn2 * 2 + lg;
            unsigned long long pp[2][4];
#pragma unroll
            for (int rh = 0; rh < 2; rh++)
#pragma unroll
                for (int jj = 0; jj < 4; jj++) pp[rh][jj] = 0ULL;
#pragma unroll
            for (int nt4 = 0; nt4 < 4; nt4++) {
                int nt = lg * 4 + nt4;
#pragma unroll
                for (int u = 0; u < 2; u++) {
                    float hv0 = fmaxf(acc[nt][u]     + b1r[nt][u], 0.0f);
                    float hv1 = fmaxf(acc[nt][2 + u] + b1r[nt][u], 0.0f);
                    int m = nt4 * 8 + 2 * tg + u;
                    const ulonglong2* wp = (const ulonglong2*)&sW2p[W2OFF(l * 32 + m)];
                    ulonglong2 wa = wp[0];   // (w0,w1),(w2,w3)
                    ulonglong2 wb = wp[1];   // (w4,w5),(w6,w7)
                    unsigned long long a0 = pack2(hv0, hv0);
                    unsigned long long a1 = pack2(hv1, hv1);
                    fma2(pp[0][0], a0, wa.x); fma2(pp[0][1], a0, wa.y);
                    fma2(pp[0][2], a0, wb.x); fma2(pp[0][3], a0, wb.y);
                    fma2(pp[1][0], a1, wa.x); fma2(pp[1][1], a1, wa.y);
                    fma2(pp[1][2], a1, wb.x); fma2(pp[1][3], a1, wb.y);
                }
            }
#pragma unroll
            for (int msk = 1; msk <= 2; msk <<= 1)
#pragma unroll
                for (int rh = 0; rh < 2; rh++)
#pragma unroll
                    for (int jj = 0; jj < 4; jj++)
                        pp[rh][jj] = add2(pp[rh][jj],
                                          __shfl_xor_sync(0xffffffffu, pp[rh][jj], msk));

#pragma unroll
            for (int rh = 0; rh < 2; rh++) {
                int j = j0 + mb + g + rh * 8;
                float mv = sMask[j];
                float v0, v1;
                unpack2(pp[rh][tg], v0, v1);
                int h0 = 2 * tg;
                float o0 = (mv != 0.0f) ? (v0 + sB2[l * 8 + h0]) : -1e30f;
                float o1 = (mv != 0.0f) ? (v1 + sB2[l * 8 + h0 + 1]) : -1e30f;
                g_refw[((size_t)(l * 64 + b * 8 + h0) * LL + i) * LL + j] = o0;
                g_refw[((size_t)(l * 64 + b * 8 + h0 + 1) * LL + i) * LL + j] = o1;
            }
        }
        __syncthreads();
    }
}

// ======== k_mm: 128x64 CTA tile, warp 32x32, raw smem + inline split (3xTF32) ========
template <int MODE>
__global__ void __launch_bounds__(256) k_mm(
        const float* __restrict__ W0, const float* __restrict__ W1,
        const float* __restrict__ W2, const float* __restrict__ b0,
        const float* __restrict__ b1, const float* __restrict__ b2) {
    __shared__ float As[128 * 20], Bs[16 * 72];
    int sel = (MODE == 1) ? (blockIdx.y >> 3) : 0;
    const float* A    = (MODE == 0) ? g_ao : g_h;
    const float* W    = (sel == 0) ? W0 : (sel == 1) ? W1 : W2;
    const float* bias = (sel == 0) ? b0 : (sel == 1) ? b1 : b2;
    int m0 = blockIdx.x * 128;
    int n0 = ((MODE == 1) ? (blockIdx.y & 7) : blockIdx.y) * 64;
    int t = threadIdx.x, lane = t & 31, wid = t >> 5;
    int g = lane >> 2, tg = lane & 3;
    int wm = wid & 3, wn = wid >> 2;
    int ar = t >> 1, ac8 = (t & 1) * 8;
    int wr = t >> 4, wc = t & 15;

    float acc[2][4][4] = {};

    for (int k0 = 0; k0 < CC; k0 += 16) {
        *(float4*)&As[ar * 20 + ac8] =
            *(const float4*)&A[(size_t)(m0 + ar) * CC + k0 + ac8];
        *(float4*)&As[ar * 20 + ac8 + 4] =
            *(const float4*)&A[(size_t)(m0 + ar) * CC + k0 + ac8 + 4];
        *(float4*)&Bs[wr * 72 + wc * 4] =
            *(const float4*)&W[(size_t)(k0 + wr) * CC + n0 + wc * 4];
        __syncthreads();

#pragma unroll
        for (int kk = 0; kk < 16; kk += 8) {
            uint32_t ah[2][4], al[2][4];
#pragma unroll
            for (int mt = 0; mt < 2; mt++) {
                int mb = wm * 32 + mt * 16;
                float xv[4];
                xv[0] = As[(mb + g) * 20 + kk + tg];
                xv[1] = As[(mb + g + 8) * 20 + kk + tg];
                xv[2] = As[(mb + g) * 20 + kk + tg + 4];
                xv[3] = As[(mb + g + 8) * 20 + kk + tg + 4];
#pragma unroll
                for (int q = 0; q < 4; q++) {
                    float hv, lv; split_tf32(xv[q], hv, lv);
                    ah[mt][q] = __float_as_uint(hv);
                    al[mt][q] = __float_as_uint(lv);
                }
            }
#pragma unroll
            for (int nt = 0; nt < 4; nt++) {
                int nb = wn * 32 + nt * 8;
                float x0 = Bs[(kk + tg) * 72 + nb + g];
                float x1 = Bs[(kk + tg + 4) * 72 + nb + g];
                float h0, l0, h1, l1;
                split_tf32(x0, h0, l0); split_tf32(x1, h1, l1);
                uint32_t bh0 = __float_as_uint(h0), bh1 = __float_as_uint(h1);
                uint32_t bl0 = __float_as_uint(l0), bl1 = __float_as_uint(l1);
#pragma unroll
                for (int mt = 0; mt < 2; mt++) {
                    mma_tf32(acc[mt][nt], ah[mt], bh0, bh1);
                    mma_tf32(acc[mt][nt], al[mt], bh0, bh1);
                    mma_tf32(acc[mt][nt], ah[mt], bl0, bl1);
                }
            }
        }
        __syncthreads();
    }

#pragma unroll
    for (int mt = 0; mt < 2; mt++) {
#pragma unroll
        for (int nt = 0; nt < 4; nt++) {
#pragma unroll
            for (int rh = 0; rh < 2; rh++) {
                int m = m0 + wm * 32 + mt * 16 + g + rh * 8;
                int n = n0 + wn * 32 + nt * 8 + 2 * tg;
                float v0 = acc[mt][nt][rh * 2]     + bias[n];
                float v1 = acc[mt][nt][rh * 2 + 1] + bias[n + 1];
                if (MODE == 0) {
                    *(float2*)&g_t1[(size_t)m * CC + n] = make_float2(v0, v1);
                } else {
                    int bi = m / LL, ii = m % LL, nh = n >> 6, d = n & 63;
                    float* OUT = (sel == 0) ? g_q : (sel == 1) ? g_k : g_v;
                    *(float2*)&OUT[((size_t)(bi * NHH + nh) * LL + ii) * DKK + d] =
                        make_float2(v0, v1);
                }
            }
        }
    }
}

// ---------- scores: 64x64 tile, 1xTF32 (softmax-protected) ----------
__global__ void __launch_bounds__(256) k_scores_mma() {
    __shared__ float As[64 * 20], Bs[64 * 20];
    int z = blockIdx.z, b = z >> 3;
    int i0 = blockIdx.x * 64, j0 = blockIdx.y * 64;
    const float* Q = g_q + (size_t)z * LL * DKK;
    const float* K = g_k + (size_t)z * LL * DKK;
    int t = threadIdx.x, lane = t & 31, wid = t >> 5;
    int g = lane >> 2, tg = lane & 3;
    int wm = wid & 1, wn = wid >> 1;
    int ar = t >> 2, ac = t & 3;
    float acc[2][2][4] = {};

    for (int k0 = 0; k0 < DKK; k0 += 16) {
        *(float4*)&As[ar * 20 + ac * 4] =
            *(const float4*)&Q[(size_t)(i0 + ar) * DKK + k0 + ac * 4];
        *(float4*)&Bs[ar * 20 + ac * 4] =
            *(const float4*)&K[(size_t)(j0 + ar) * DKK + k0 + ac * 4];
        __syncthreads();

#pragma unroll
        for (int kk = 0; kk < 16; kk += 8) {
            uint32_t ah[2][4];
#pragma unroll
            for (int mt = 0; mt < 2; mt++) {
                int mb = wm * 32 + mt * 16;
                ah[mt][0] = __float_as_uint(to_tf32(As[(mb + g) * 20 + kk + tg]));
                ah[mt][1] = __float_as_uint(to_tf32(As[(mb + g + 8) * 20 + kk + tg]));
                ah[mt][2] = __float_as_uint(to_tf32(As[(mb + g) * 20 + kk + tg + 4]));
                ah[mt][3] = __float_as_uint(to_tf32(As[(mb + g + 8) * 20 + kk + tg + 4]));
            }
#pragma unroll
            for (int nt = 0; nt < 2; nt++) {
                int nb = wn * 16 + nt * 8;
                uint32_t bh0 = __float_as_uint(to_tf32(Bs[(nb + g) * 20 + kk + tg]));
                uint32_t bh1 = __float_as_uint(to_tf32(Bs[(nb + g) * 20 + kk + tg + 4]));
#pragma unroll
                for (int mt = 0; mt < 2; mt++)
                    mma_tf32(acc[mt][nt], ah[mt], bh0, bh1);
            }
        }
        __syncthreads();
    }

    float* out = g_sc + (size_t)z * LL * LL;
#pragma unroll
    for (int mt = 0; mt < 2; mt++) {
#pragma unroll
        for (int rh = 0; rh < 2; rh++) {
            int i = i0 + wm * 32 + mt * 16 + g + rh * 8;
            float mi = g_mask[b * LL + i];
#pragma unroll
            for (int nt = 0; nt < 2; nt++) {
                int j = j0 + wn * 16 + nt * 8 + 2 * tg;
                float mj0 = g_mask[b * LL + j];
                float mj1 = g_mask[b * LL + j + 1];
                float v0 = (mi != 0.0f && mj0 != 0.0f) ? acc[mt][nt][rh * 2] * 0.125f : -1e30f;
                float v1 = (mi != 0.0f && mj1 != 0.0f) ? acc[mt][nt][rh * 2 + 1] * 0.125f : -1e30f;
                *(float2*)&out[(size_t)i * LL + j] = make_float2(v0, v1);
            }
        }
    }
}

// ---------- dual softmax + combine ----------
__global__ void k_softcomb(int l) {
    int gw = blockIdx.x * 4 + (threadIdx.x >> 5);
    int lane = threadIdx.x & 31;
    int row_i = gw % LL;
    int z = gw / LL;
    int b = z >> 3;
    float* sc = g_sc + (size_t)z * LL * LL + (size_t)row_i * LL;
    if (g_mask[b * LL + row_i] == 0.0f) {
        for (int j = lane; j < LL; j += 32) sc[j] = 0.0f;
        return;
    }
    const float* rw = g_refw + (((size_t)l * BB * NHH + z) * LL + row_i) * LL;
    float vals[12], rv[12];
    float mx = -3.4e38f, rmx = -3.4e38f;
#pragma unroll
    for (int r = 0; r < 12; r++) {
        vals[r] = sc[lane + r * 32]; mx = fmaxf(mx, vals[r]);
        rv[r] = rw[lane + r * 32];   rmx = fmaxf(rmx, rv[r]);
    }
#pragma unroll
    for (int o = 16; o > 0; o >>= 1) {
        mx  = fmaxf(mx,  __shfl_xor_sync(0xffffffffu, mx, o));
        rmx = fmaxf(rmx, __shfl_xor_sync(0xffffffffu, rmx, o));
    }
    float s = 0.0f, rs = 0.0f;
#pragma unroll
    for (int r = 0; r < 12; r++) {
        vals[r] = __expf(vals[r] - mx); s += vals[r];
        rv[r]   = __expf(rv[r] - rmx);  rs += rv[r];
    }
#pragma unroll
    for (int o = 16; o > 0; o >>= 1) {
        s  += __shfl_xor_sync(0xffffffffu, s, o);
        rs += __shfl_xor_sync(0xffffffffu, rs, o);
    }
    float inv = 0.5f / s, rinv = 0.5f / rs;
#pragma unroll
    for (int r = 0; r < 12; r++)
        sc[lane + r * 32] = vals[r] * inv + rv[r] * rinv;
}

// ---------- av: 64x64 tile, K=384, raw smem + inline split (3xTF32) ----------
__global__ void __launch_bounds__(256) k_av_mma() {
    __shared__ float As[64 * 20], Bs[16 * 72];
    int z = blockIdx.y, b = z >> 3, nh = z & 7;
    const float* Am = g_sc + (size_t)z * LL * LL;
    const float* V  = g_v + (size_t)z * LL * DKK;
    int m0 = blockIdx.x * 64;
    int t = threadIdx.x, lane = t & 31, wid = t >> 5;
    int g = lane >> 2, tg = lane & 3;
    int wm = wid & 1, wn = wid >> 1;
    int ar = t >> 2, ac = t & 3;
    int wr = t >> 4, wc = t & 15;
    float acc[2][2][4] = {};

    for (int k0 = 0; k0 < LL; k0 += 16) {
        *(float4*)&As[ar * 20 + ac * 4] =
            *(const float4*)&Am[(size_t)(m0 + ar) * LL + k0 + ac * 4];
        *(float4*)&Bs[wr * 72 + wc * 4] =
            *(const float4*)&V[(size_t)(k0 + wr) * DKK + wc * 4];
        __syncthreads();

#pragma unroll
        for (int kk = 0; kk < 16; kk += 8) {
            uint32_t ah[2][4], al[2][4];
#pragma unroll
            for (int mt = 0; mt < 2; mt++) {
                int mb = wm * 32 + mt * 16;
                float xv[4];
                xv[0] = As[(mb + g) * 20 + kk + tg];
                xv[1] = As[(mb + g + 8) * 20 + kk + tg];
                xv[2] = As[(mb + g) * 20 + kk + tg + 4];
                xv[3] = As[(mb + g + 8) * 20 + kk + tg + 4];
#pragma unroll
                for (int q = 0; q < 4; q++) {
                    float hv, lv; split_tf32(xv[q], hv, lv);
                    ah[mt][q] = __float_as_uint(hv);
                    al[mt][q] = __float_as_uint(lv);
                }
            }
#pragma unroll
            for (int nt = 0; nt < 2; nt++) {
                int nb = wn * 16 + nt * 8;
                float x0 = Bs[(kk + tg) * 72 + nb + g];
                float x1 = Bs[(kk + tg + 4) * 72 + nb + g];
                float h0, l0, h1, l1;
                split_tf32(x0, h0, l0); split_tf32(x1, h1, l1);
                uint32_t bh0 = __float_as_uint(h0), bh1 = __float_as_uint(h1);
                uint32_t bl0 = __float_as_uint(l0), bl1 = __float_as_uint(l1);
#pragma unroll
                for (int mt = 0; mt < 2; mt++) {
                    mma_tf32(acc[mt][nt], ah[mt], bh0, bh1);
                    mma_tf32(acc[mt][nt], al[mt], bh0, bh1);
                    mma_tf32(acc[mt][nt], ah[mt], bl0, bl1);
                }
            }
        }
        __syncthreads();
    }

#pragma unroll
    for (int mt = 0; mt < 2; mt++) {
#pragma unroll
        for (int nt = 0; nt < 2; nt++) {
#pragma unroll
            for (int rh = 0; rh < 2; rh++) {
                int i = m0 + wm * 32 + mt * 16 + g + rh * 8;
                int d = wn * 16 + nt * 8 + 2 * tg;
                *(float2*)&g_ao[((size_t)(b * LL + i)) * CC + nh * DKK + d] =
                    make_float2(acc[mt][nt][rh * 2], acc[mt][nt][rh * 2 + 1]);
            }
        }
    }
}

// ---------- residual + layernorm ----------
template <int FINAL>
__global__ void k_ln(const float* __restrict__ gam, const float* __restrict__ bet) {
    __shared__ float red[8];
    int r = blockIdx.x, t = threadIdx.x;
    const float* a = g_h + (size_t)r * CC;
    const float* bb = g_t1 + (size_t)r * CC;
    float v[4];
    float s = 0.0f;
#pragma unroll
    for (int q = 0; q < 4; q++) {
        int cidx = t + q * 128;
        float x = FINAL ? a[cidx] : (a[cidx] + bb[cidx]);
        v[q] = x;
        s += x;
    }
#pragma unroll
    for (int o = 16; o > 0; o >>= 1) s += __shfl_xor_sync(0xffffffffu, s, o);
    if ((t & 31) == 0) red[t >> 5] = s;
    __syncthreads();
    float mu = (red[0] + red[1] + red[2] + red[3]) * (1.0f / 512.0f);
    float vs = 0.0f;
#pragma unroll
    for (int q = 0; q < 4; q++) { float d = v[q] - mu; vs += d * d; }
#pragma unroll
    for (int o = 16; o > 0; o >>= 1) vs += __shfl_xor_sync(0xffffffffu, vs, o);
    if ((t & 31) == 0) red[4 + (t >> 5)] = vs;
    __syncthreads();
    float var = (red[4] + red[5] + red[6] + red[7]) * (1.0f / 512.0f);
    float rsr = rsqrtf(var + 1e-5f);
    float* out = FINAL ? (g_t1 + (size_t)r * CC) : (g_h + (size_t)r * CC);
#pragma unroll
    for (int q = 0; q < 4; q++) {
        int cidx = t + q * 128;
        out[cidx] = (v[q] - mu) * rsr * gam[cidx] + bet[cidx];
    }
}

// ---------- final masked sum ----------
__global__ void k_finred(float* __restrict__ out) {
    int b = blockIdx.x;
    int cidx = blockIdx.y * 128 + threadIdx.x;
    float s = 0.0f;
#pragma unroll 4
    for (int i = 0; i < LL; i++)
        s += g_mask[b * LL + i] * g_t1[((size_t)(b * LL + i)) * CC + cidx];
    out[b * CC + cidx] = s;
}

// ---------- host launch ----------
extern "C" void kernel_launch(void* const* d_in, const int* in_sizes, int n_in,
                              void* d_out, int out_size) {
    const float* x            = (const float*)d_in[0];
    const unsigned char* mraw = (const unsigned char*)d_in[1];
    const float* refCov       = (const float*)d_in[2];
    const float* Wq  = (const float*)d_in[3];
    const float* bq  = (const float*)d_in[4];
    const float* Wk  = (const float*)d_in[5];
    const float* bk  = (const float*)d_in[6];
    const float* Wv  = (const float*)d_in[7];
    const float* bv  = (const float*)d_in[8];
    const float* Wo  = (const float*)d_in[9];
    const float* bo  = (const float*)d_in[10];
    const float* Wr1 = (const float*)d_in[11];
    const float* br1 = (const float*)d_in[12];
    const float* Wr2 = (const float*)d_in[13];
    const float* br2 = (const float*)d_in[14];
    const float* ln_g = (const float*)d_in[15];
    const float* ln_b = (const float*)d_in[16];
    const float* fn_g = (const float*)d_in[17];
    const float* fn_b = (const float*)d_in[18];
    (void)in_sizes; (void)n_in; (void)out_size;

    cudaFuncSetAttribute(k_ref, cudaFuncAttributeMaxDynamicSharedMemorySize,
                         REF_SMEM_FLOATS * (int)sizeof(float));

    k_detect<<<1, 256>>>(mraw);
    k_mask<<<(BB * LL + 255) / 256, 256>>>(mraw);
    k_hinit<<<(BB * LL * CC) / 256, 256>>>(x);
    k_ref<<<BB * LL, 256, REF_SMEM_FLOATS * sizeof(float)>>>(refCov, Wr1, br1, Wr2, br2);

    for (int l = 0; l < NLL; l++) {
        const float* wq = Wq + (size_t)l * CC * CC;
        const float* wk = Wk + (size_t)l * CC * CC;
        const float* wv = Wv + (size_t)l * CC * CC;
        const float* wo = Wo + (size_t)l * CC * CC;
        k_mm<1><<<dim3(24, 24), 256>>>(wq, wk, wv, bq + l * CC, bk + l * CC, bv + l * CC);
        k_scores_mma<<<dim3(6, 6, BB * NHH), 256>>>();
        k_softcomb<<<(BB * NHH * LL) / 4, 128>>>(l);
        k_av_mma<<<dim3(6, BB * NHH), 256>>>();
        k_mm<0><<<dim3(24, 8), 256>>>(wo, bo + l * CC, nullptr, bo + l * CC, nullptr, nullptr);
        k_ln<0><<<BB * LL, 128>>>(ln_g + l * CC, ln_b + l * CC);
    }
    k_ln<1><<<BB * LL, 128>>>(fn_g, fn_b);
    k_finred<<<dim3(BB, CC / 128), 128>>>((float*)d_out);
}